// round 14
// baseline (speedup 1.0000x reference)
#include <cuda_runtime.h>
#include <cuda_bf16.h>
#include <cstdint>
#include <cstddef>
#include <math.h>

#define B_   2
#define N_   2048
#define HID_ 1024
#define H_   16
#define D_   64
#define BH_  (B_*H_)     // 32
#define M_   (B_*N_)     // 4096
#define TOPK_ 64

// scratch
__device__ float g_Vh[BH_*N_*D_];
__device__ unsigned g_S[134217728];           // 537 MB [bh][q][k]  FLIPPED fp32 bits
__device__ float g_ctx[M_*HID_];

// 3-term splits of (projected, scaled) Q / K  (h/m/l each), written directly
// by the projection epilogue
__device__ __nv_bfloat16 g_Q3[3][BH_*N_*D_];
__device__ __nv_bfloat16 g_K3[3][BH_*N_*D_];

// ---------------------------------------------------------------------------
#define LDSM_X4(r0,r1,r2,r3,addr) \
    asm volatile("ldmatrix.sync.aligned.m8n8.x4.shared.b16 {%0,%1,%2,%3}, [%4];" \
        : "=r"(r0), "=r"(r1), "=r"(r2), "=r"(r3) : "r"(addr))
#define LDSM_X2(r0,r1,addr) \
    asm volatile("ldmatrix.sync.aligned.m8n8.x2.shared.b16 {%0,%1}, [%2];" \
        : "=r"(r0), "=r"(r1) : "r"(addr))
#define MMA16816(c0,c1,c2,c3,a0,a1,a2,a3,b0,b1) \
    asm volatile("mma.sync.aligned.m16n8k16.row.col.f32.bf16.bf16.f32 " \
        "{%0,%1,%2,%3}, {%4,%5,%6,%7}, {%8,%9}, {%0,%1,%2,%3};" \
        : "+f"(c0), "+f"(c1), "+f"(c2), "+f"(c3) \
        : "r"(a0), "r"(a1), "r"(a2), "r"(a3), "r"(b0), "r"(b1))

__device__ __forceinline__ uint32_t smem_u32(const void* p) {
    uint32_t a;
    asm("{ .reg .u64 t; cvta.to.shared.u64 t, %1; cvt.u32.u64 %0, t; }"
        : "=r"(a) : "l"(p));
    return a;
}
__device__ __forceinline__ uint32_t bf2pack(__nv_bfloat16 a, __nv_bfloat16 b) {
    __nv_bfloat162 t; t.x = a; t.y = b;
    return *(uint32_t*)&t;
}
__device__ __forceinline__ unsigned fflip(float f) {
    unsigned u = __float_as_uint(f);
    return (u & 0x80000000u) ? ~u : (u | 0x80000000u);
}
__device__ __forceinline__ float funflip(unsigned u) {
    unsigned v = (u & 0x80000000u) ? (u & 0x7FFFFFFFu) : ~u;
    return __uint_as_float(v);
}

// ---------------------------------------------------------------------------
// fp32 SGEMM body (mainloop bit-identical); epilogue emits split3 bf16 planes
// ---------------------------------------------------------------------------
#define ASF(cur,kk,c) Asp[((cur)*8+(kk))*128+(c)]
#define BSF(cur,kk,c) Bsp[((cur)*8+(kk))*128+(c)]

__device__ __forceinline__ void sgemm_split3_body(
    const float* __restrict__ X, const float* __restrict__ W,
    const float* __restrict__ bias,
    __nv_bfloat16* __restrict__ Oh, __nv_bfloat16* __restrict__ Om,
    __nv_bfloat16* __restrict__ Ol,
    float oscale, int n0, int o0, char* fbuf)
{
    const int K = HID_;
    float* Asp = (float*)fbuf;            // [2][8][128] = 8192 B
    float* Bsp = (float*)(fbuf + 8192);   // 8192 B
    int tid = threadIdx.x;

    int lrow = tid >> 1;
    int lkq  = (tid & 1) * 4;
    const float* Xp = X + (size_t)(n0 + lrow) * K + lkq;
    const float* Wp = W + (size_t)(o0 + lrow) * K + lkq;

    {
        float4 xa = *(const float4*)Xp;
        float4 wa = *(const float4*)Wp;
        ASF(0, lkq+0, lrow) = xa.x; ASF(0, lkq+1, lrow) = xa.y;
        ASF(0, lkq+2, lrow) = xa.z; ASF(0, lkq+3, lrow) = xa.w;
        BSF(0, lkq+0, lrow) = wa.x; BSF(0, lkq+1, lrow) = wa.y;
        BSF(0, lkq+2, lrow) = wa.z; BSF(0, lkq+3, lrow) = wa.w;
    }
    __syncthreads();

    int tx = tid & 15, ty = tid >> 4;
    float c[8][8];
#pragma unroll
    for (int i = 0; i < 8; i++)
#pragma unroll
        for (int j = 0; j < 8; j++) c[i][j] = 0.f;

    const int NSTEP = K / 8;
#pragma unroll 2
    for (int k0 = 0; k0 < NSTEP; k0++) {
        int cur = k0 & 1;
        float4 xn, wn;
        if (k0 < NSTEP - 1) {
            xn = *(const float4*)(Xp + (k0 + 1) * 8);
            wn = *(const float4*)(Wp + (k0 + 1) * 8);
        }
#pragma unroll
        for (int kk = 0; kk < 8; kk++) {
            float a[8], b[8];
            *(float4*)&a[0] = *(const float4*)&ASF(cur, kk, ty*8);
            *(float4*)&a[4] = *(const float4*)&ASF(cur, kk, ty*8+4);
            *(float4*)&b[0] = *(const float4*)&BSF(cur, kk, tx*8);
            *(float4*)&b[4] = *(const float4*)&BSF(cur, kk, tx*8+4);
#pragma unroll
            for (int i = 0; i < 8; i++)
#pragma unroll
                for (int j = 0; j < 8; j++)
                    c[i][j] += a[i] * b[j];
        }
        if (k0 < NSTEP - 1) {
            int nxt = cur ^ 1;
            ASF(nxt, lkq+0, lrow) = xn.x; ASF(nxt, lkq+1, lrow) = xn.y;
            ASF(nxt, lkq+2, lrow) = xn.z; ASF(nxt, lkq+3, lrow) = xn.w;
            BSF(nxt, lkq+0, lrow) = wn.x; BSF(nxt, lkq+1, lrow) = wn.y;
            BSF(nxt, lkq+2, lrow) = wn.z; BSF(nxt, lkq+3, lrow) = wn.w;
            __syncthreads();
        }
    }

    float bfr[8];
#pragma unroll
    for (int j = 0; j < 8; j++) bfr[j] = __ldg(bias + o0 + tx*8 + j);

#pragma unroll
    for (int i = 0; i < 8; i++) {
        int n = n0 + ty * 8 + i;
        int o = o0 + tx * 8;
        int b = n >> 11, nn = n & 2047;
        int h = o >> 6,  d  = o & 63;
        size_t idx = (((size_t)(b * H_ + h) * N_) + nn) * D_ + d;

        float val[8];
#pragma unroll
        for (int j = 0; j < 8; j++) val[j] = (c[i][j] + bfr[j]) * oscale;

        __nv_bfloat16 hh[8], mm[8], ll[8];
#pragma unroll
        for (int j = 0; j < 8; j++) {
            hh[j] = __float2bfloat16_rn(val[j]);
            float r1 = val[j] - __bfloat162float(hh[j]);
            mm[j] = __float2bfloat16_rn(r1);
            float r2 = r1 - __bfloat162float(mm[j]);
            ll[j] = __float2bfloat16_rn(r2);
        }
        uint4 hv, mv, lv;
        hv.x = bf2pack(hh[0], hh[1]); hv.y = bf2pack(hh[2], hh[3]);
        hv.z = bf2pack(hh[4], hh[5]); hv.w = bf2pack(hh[6], hh[7]);
        mv.x = bf2pack(mm[0], mm[1]); mv.y = bf2pack(mm[2], mm[3]);
        mv.z = bf2pack(mm[4], mm[5]); mv.w = bf2pack(mm[6], mm[7]);
        lv.x = bf2pack(ll[0], ll[1]); lv.y = bf2pack(ll[2], ll[3]);
        lv.z = bf2pack(ll[4], ll[5]); lv.w = bf2pack(ll[6], ll[7]);
        *(uint4*)(Oh + idx) = hv;
        *(uint4*)(Om + idx) = mv;
        *(uint4*)(Ol + idx) = lv;
    }
}

// ---------------------------------------------------------------------------
// HMMA split-bf16 GEMM body, on-the-fly split, DOUBLE-BUFFERED smem stages.
// MMA operand values & order identical to R12 => bit-identical outputs.
// fbuf = dynamic smem, 2 stages x 40960 B.
// ---------------------------------------------------------------------------
#define TS_    5120          // tile size in bf16 entries (128 rows * 40)
#define STGB_  40960         // stage bytes (4 tiles)

__device__ __forceinline__ void hmma_f32_body(
    const float* __restrict__ Af, const float* __restrict__ Bf,
    const float* __restrict__ bias, float* __restrict__ Out,
    int mode, int n0, int o0, char* fbuf)
{
    int tid  = threadIdx.x;
    int wid  = tid >> 5, lane = tid & 31;
    int wm   = wid >> 2;
    int wn   = wid & 3;

    uint32_t smb = smem_u32(fbuf);

    float c[4][4][4];
#pragma unroll
    for (int mt = 0; mt < 4; mt++)
#pragma unroll
        for (int nt = 0; nt < 4; nt++)
#pragma unroll
            for (int r = 0; r < 4; r++) c[mt][nt][r] = 0.f;

    int rowm[4], segm[4];
    const float* gbase[4];
#pragma unroll
    for (int j = 0; j < 4; j++) {
        int isB  = j >> 1;
        int sub  = ((j & 1) << 8) + tid;       // 0..511
        rowm[j] = sub >> 2; segm[j] = sub & 3;
        const float* base = isB ? Bf : Af;
        int grow = (isB ? o0 : n0) + rowm[j];
        gbase[j] = base + (size_t)grow * HID_ + segm[j] * 8;
    }
    uint32_t soffh[4], soffl[4];
#pragma unroll
    for (int j = 0; j < 4; j++) {
        int isB = j >> 1;
        uint32_t e = (uint32_t)(rowm[j] * 40 + segm[j] * 8);
        soffh[j] = (uint32_t)(((isB ? 2 : 0) * TS_ + e) * 2);
        soffl[j] = (uint32_t)(((isB ? 3 : 1) * TS_ + e) * 2);
    }

    uint32_t laneA = (uint32_t)((lane & 15) * 80 + (lane >> 4) * 16);
    uint32_t laneB = (uint32_t)((lane & 7) * 80 + ((lane >> 3) & 1) * 16);
    uint32_t aBase0 = smb + (uint32_t)(wm * 64 * 80) + laneA;
    uint32_t bBase0 = smb + (uint32_t)(wn * 32 * 80) + laneB;

    float4 pf0[4], pf1[4];
#pragma unroll
    for (int j = 0; j < 4; j++) {
        pf0[j] = *(const float4*)gbase[j];
        pf1[j] = *(const float4*)(gbase[j] + 4);
    }
    // store stage 0
#pragma unroll
    for (int j = 0; j < 4; j++) {
        float fv[8] = {pf0[j].x, pf0[j].y, pf0[j].z, pf0[j].w,
                       pf1[j].x, pf1[j].y, pf1[j].z, pf1[j].w};
        __nv_bfloat16 hh[8], ll[8];
#pragma unroll
        for (int e = 0; e < 8; e++) {
            hh[e] = __float2bfloat16_rn(fv[e]);
            ll[e] = __float2bfloat16_rn(fv[e] - __bfloat162float(hh[e]));
        }
        uint4 hv, lv;
        hv.x = bf2pack(hh[0], hh[1]); hv.y = bf2pack(hh[2], hh[3]);
        hv.z = bf2pack(hh[4], hh[5]); hv.w = bf2pack(hh[6], hh[7]);
        lv.x = bf2pack(ll[0], ll[1]); lv.y = bf2pack(ll[2], ll[3]);
        lv.z = bf2pack(ll[4], ll[5]); lv.w = bf2pack(ll[6], ll[7]);
        *(uint4*)(fbuf + soffh[j]) = hv;
        *(uint4*)(fbuf + soffl[j]) = lv;
    }
    __syncthreads();

    for (int kc = 0; kc < 32; kc++) {
        int cur = kc & 1;
        if (kc < 31) {
#pragma unroll
            for (int j = 0; j < 4; j++) {
                pf0[j] = *(const float4*)(gbase[j] + (kc + 1) * 32);
                pf1[j] = *(const float4*)(gbase[j] + (kc + 1) * 32 + 4);
            }
        }

        uint32_t stg = (uint32_t)(cur * STGB_);
#pragma unroll
        for (int pass = 0; pass < 3; pass++) {
            uint32_t aT = aBase0 + stg + (uint32_t)(((pass == 2) ? TS_ : 0) * 2);
            uint32_t bT = bBase0 + stg + (uint32_t)((((pass == 1) ? 3 : 2) * TS_) * 2);
#pragma unroll
            for (int k16 = 0; k16 < 2; k16++) {
                uint32_t a[4][4];
#pragma unroll
                for (int mt = 0; mt < 4; mt++)
                    LDSM_X4(a[mt][0], a[mt][1], a[mt][2], a[mt][3],
                            aT + (uint32_t)(mt * 1280 + k16 * 32));
                uint32_t bf[4][2];
#pragma unroll
                for (int nt = 0; nt < 4; nt++)
                    LDSM_X2(bf[nt][0], bf[nt][1],
                            bT + (uint32_t)(nt * 640 + k16 * 32));
#pragma unroll
                for (int mt = 0; mt < 4; mt++)
#pragma unroll
                    for (int nt = 0; nt < 4; nt++)
                        MMA16816(c[mt][nt][0], c[mt][nt][1], c[mt][nt][2], c[mt][nt][3],
                                 a[mt][0], a[mt][1], a[mt][2], a[mt][3],
                                 bf[nt][0], bf[nt][1]);
            }
        }

        if (kc < 31) {
            // store NEXT stage (other buffer: safe to overlap with this MMA phase,
            // since all warps finished reading it before the previous sync)
            char* nb = fbuf + (cur ^ 1) * STGB_;
#pragma unroll
            for (int j = 0; j < 4; j++) {
                float fv[8] = {pf0[j].x, pf0[j].y, pf0[j].z, pf0[j].w,
                               pf1[j].x, pf1[j].y, pf1[j].z, pf1[j].w};
                __nv_bfloat16 hh[8], ll[8];
#pragma unroll
                for (int e = 0; e < 8; e++) {
                    hh[e] = __float2bfloat16_rn(fv[e]);
                    ll[e] = __float2bfloat16_rn(fv[e] - __bfloat162float(hh[e]));
                }
                uint4 hv, lv;
                hv.x = bf2pack(hh[0], hh[1]); hv.y = bf2pack(hh[2], hh[3]);
                hv.z = bf2pack(hh[4], hh[5]); hv.w = bf2pack(hh[6], hh[7]);
                lv.x = bf2pack(ll[0], ll[1]); lv.y = bf2pack(ll[2], ll[3]);
                lv.z = bf2pack(ll[4], ll[5]); lv.w = bf2pack(ll[6], ll[7]);
                *(uint4*)(nb + soffh[j]) = hv;
                *(uint4*)(nb + soffl[j]) = lv;
            }
            __syncthreads();
        }
    }

    int row_l = lane >> 2;
    int col_l = (lane & 3) * 2;
#pragma unroll
    for (int nt = 0; nt < 4; nt++) {
        int o = o0 + wn * 32 + nt * 8 + col_l;
        float bv0 = __ldg(bias + o);
        float bv1 = __ldg(bias + o + 1);
#pragma unroll
        for (int mt = 0; mt < 4; mt++) {
            int n = n0 + wm * 64 + mt * 16 + row_l;
#pragma unroll
            for (int half = 0; half < 2; half++) {
                int nn2 = n + half * 8;
                size_t idx;
                if (mode == 0) {
                    int b = nn2 >> 11, nr = nn2 & 2047;
                    int h = o >> 6,  d0 = o & 63;
                    idx = (((size_t)(b * H_ + h) * N_) + nr) * D_ + d0;
                } else {
                    idx = (size_t)nn2 * HID_ + o;
                }
                float2 vv;
                vv.x = c[mt][nt][half * 2 + 0] + bv0;
                vv.y = c[mt][nt][half * 2 + 1] + bv1;
                *(float2*)(Out + idx) = vv;
            }
        }
    }
}

// ---------------------------------------------------------------------------
// fused_front: Q/K fp32 proj (split3 epilogue) + V HMMA proj (double-buffered)
// ---------------------------------------------------------------------------
__global__ __launch_bounds__(256, 2) void fused_front(
    const float* __restrict__ q,  const float* __restrict__ wq_w,
    const float* __restrict__ wq_b,
    const float* __restrict__ k,  const float* __restrict__ wk_w,
    const float* __restrict__ wk_b,
    const float* __restrict__ v,  const float* __restrict__ wv_w,
    const float* __restrict__ wv_b, float* __restrict__ Vh)
{
    extern __shared__ __align__(16) char fbuf[];
    int id = blockIdx.x;
    int r  = id % 3;
    int g  = id / 3;

    if (r < 2) {
        int t   = g * 2 + r;          // 0..511
        int z   = t >> 8;             // 0 = Q, 1 = K
        int rem = t & 255;
        int o0  = (rem & 7) * 128;
        int n0  = (rem >> 3) * 128;
        if (z == 0)
            sgemm_split3_body(q, wq_w, wq_b,
                              g_Q3[0], g_Q3[1], g_Q3[2],
                              0.125f, n0, o0, fbuf);
        else
            sgemm_split3_body(k, wk_w, wk_b,
                              g_K3[0], g_K3[1], g_K3[2],
                              1.0f, n0, o0, fbuf);
    } else {
        int t  = g;                   // 0..255
        int o0 = (t & 7) * 128;
        int n0 = (t >> 3) * 128;
        hmma_f32_body(v, wv_w, wv_b, Vh, 0, n0, o0, fbuf);
    }
}

// O projection standalone (after topk)
__global__ __launch_bounds__(256, 2) void hmma_o(
    const float* __restrict__ ctx, const float* __restrict__ wo_w,
    const float* __restrict__ wo_b, float* __restrict__ Out)
{
    extern __shared__ __align__(16) char fbuf[];
    hmma_f32_body(ctx, wo_w, wo_b, Out, 1,
                  blockIdx.y * 128, blockIdx.x * 128, fbuf);
}

// ---------------------------------------------------------------------------
// Scores (resident tiles, verbatim R12) -- epilogue stores FLIPPED bits.
// ---------------------------------------------------------------------------
#define STRB_ 144                 // row stride bytes
#define TSB_  (128 * STRB_)       // tile bytes = 18432

__global__ __launch_bounds__(256, 2) void scores_s3r(void)
{
    extern __shared__ __align__(16) char dsm[];
    int tid  = threadIdx.x;
    int wid  = tid >> 5, lane = tid & 31;
    int wm   = wid >> 2;
    int wn   = wid & 3;
    int bh   = blockIdx.z;
    int k0   = blockIdx.x * 128;
    int q0   = blockIdx.y * 128;

    uint32_t smb = smem_u32(dsm);

    const __nv_bfloat16* tsrc[6] = {
        g_Q3[0] + (size_t)bh * N_ * D_, g_Q3[1] + (size_t)bh * N_ * D_,
        g_Q3[2] + (size_t)bh * N_ * D_, g_K3[0] + (size_t)bh * N_ * D_,
        g_K3[1] + (size_t)bh * N_ * D_, g_K3[2] + (size_t)bh * N_ * D_ };

#pragma unroll
    for (int t = 0; t < 6; t++) {
        int r0 = (t < 3) ? q0 : k0;
#pragma unroll
        for (int it = 0; it < 4; it++) {
            int sub = it * 256 + tid;
            int row = sub >> 3, seg = sub & 7;
            *(uint4*)(dsm + t * TSB_ + row * STRB_ + seg * 16) =
                *(const uint4*)(tsrc[t] + (size_t)(r0 + row) * D_ + seg * 8);
        }
    }
    __syncthreads();

    float c[4][4][4];
#pragma unroll
    for (int mt = 0; mt < 4; mt++)
#pragma unroll
        for (int nt = 0; nt < 4; nt++)
#pragma unroll
            for (int r = 0; r < 4; r++) c[mt][nt][r] = 0.f;

    uint32_t laneA = (uint32_t)((lane & 15) * STRB_ + (lane >> 4) * 16);
    uint32_t laneB = (uint32_t)((lane & 7) * STRB_ + ((lane >> 3) & 1) * 16);
    uint32_t aBase0 = smb + (uint32_t)(wm * 64 * STRB_) + laneA;
    uint32_t bBase0 = smb + (uint32_t)(wn * 32 * STRB_) + laneB;

#pragma unroll
    for (int rnd = 0; rnd < 2; rnd++) {
#pragma unroll
        for (int kc = 0; kc < 2; kc++) {
            int npass = rnd ? 2 : 4;
            for (int p = 0; p < npass; p++) {
                int at, bt;
                if (rnd == 0) { at = p >> 1;           bt = 3 + (p & 1); }
                else          { at = (p == 0) ? 0 : 2; bt = (p == 0) ? 5 : 3; }
                uint32_t aT = aBase0 + (uint32_t)(at * TSB_);
                uint32_t bT = bBase0 + (uint32_t)(bt * TSB_);
#pragma unroll
                for (int k16 = 0; k16 < 2; k16++) {
                    uint32_t coloff = (uint32_t)(kc * 64 + k16 * 32);
                    uint32_t a[4][4];
#pragma unroll
                    for (int mt = 0; mt < 4; mt++)
                        LDSM_X4(a[mt][0], a[mt][1], a[mt][2], a[mt][3],
                                aT + (uint32_t)(mt * 16 * STRB_) + coloff);
                    uint32_t bf[4][2];
#pragma unroll
                    for (int nt = 0; nt < 4; nt++)
                        LDSM_X2(bf[nt][0], bf[nt][1],
                                bT + (uint32_t)(nt * 8 * STRB_) + coloff);
#pragma unroll
                    for (int mt = 0; mt < 4; mt++)
#pragma unroll
                        for (int nt = 0; nt < 4; nt++)
                            MMA16816(c[mt][nt][0], c[mt][nt][1], c[mt][nt][2], c[mt][nt][3],
                                     a[mt][0], a[mt][1], a[mt][2], a[mt][3],
                                     bf[nt][0], bf[nt][1]);
                }
            }
        }
    }

    int row_l = lane >> 2;
    int col_l = (lane & 3) * 2;
    unsigned* Sb = g_S + (size_t)bh * N_ * N_;
#pragma unroll
    for (int nt = 0; nt < 4; nt++) {
        int o = k0 + wn * 32 + nt * 8 + col_l;
#pragma unroll
        for (int mt = 0; mt < 4; mt++) {
            int n = q0 + wm * 64 + mt * 16 + row_l;
#pragma unroll
            for (int half = 0; half < 2; half++) {
                int qq = n + half * 8;
                uint2 vv;
                vv.x = fflip(c[mt][nt][half * 2 + 0]);
                vv.y = fflip(c[mt][nt][half * 2 + 1]);
                *(uint2*)(Sb + (size_t)qq * N_ + o) = vv;
            }
        }
    }
}

// ---------------------------------------------------------------------------
// topk_v4 (verbatim R12), 8 warps/block
// ---------------------------------------------------------------------------
#define CAP_ 320

__global__ __launch_bounds__(256) void topk_pv_kernel(void)
{
    __shared__ unsigned       candV[8][CAP_];
    __shared__ unsigned short candI[8][CAP_];
    __shared__ int   sk[8][64];
    __shared__ float sv[8][64];
    __shared__ float pw[8][64];
    __shared__ int   ek[8][64];

    int w    = threadIdx.x >> 5;
    int lane = threadIdx.x & 31;
    int gq   = blockIdx.x * 8 + w;
    int bh   = gq >> 11;
    int qr   = gq & 2047;
    unsigned ltmask = (1u << lane) - 1u;

    const unsigned* Sb = g_S + ((size_t)bh * N_ + qr) * N_;

    unsigned u[64];
    unsigned m1 = 0u, m2 = 0u;
#pragma unroll
    for (int it = 0; it < 16; it++) {
        uint4 f = ((const uint4*)Sb)[it * 32 + lane];
        u[it*4+0] = f.x; u[it*4+1] = f.y; u[it*4+2] = f.z; u[it*4+3] = f.w;
#pragma unroll
        for (int r = 0; r < 4; r++) {
            unsigned x = u[it*4+r];
            if (x > m1) { m2 = m1; m1 = x; }
            else if (x > m2) { m2 = x; }
        }
    }
    unsigned T0 = __reduce_min_sync(0xffffffffu, m2);

    int cnt = 0;
#pragma unroll
    for (int i = 0; i < 64; i++) cnt += (u[i] >= T0);
    int off = cnt;
#pragma unroll
    for (int d = 1; d < 32; d <<= 1) {
        int t = __shfl_up_sync(0xffffffffu, off, d);
        if (lane >= d) off += t;
    }
    int nc = __shfl_sync(0xffffffffu, off, 31);
    off -= cnt;

    if (nc <= CAP_) {
        int o2 = off;
#pragma unroll
        for (int i = 0; i < 64; i++) {
            if (u[i] >= T0) {
                candV[w][o2] = u[i];
                candI[w][o2] = (unsigned short)((i >> 2) * 128 + lane * 4 + (i & 3));
                o2++;
            }
        }
    }
    __syncwarp();

    unsigned X = 0u;
    if (nc <= CAP_) {
        unsigned cu[CAP_/32];
        unsigned short ci[CAP_/32];
#pragma unroll
        for (int jj = 0; jj < CAP_/32; jj++) {
            int idx = lane + jj * 32;
            cu[jj] = (idx < nc) ? candV[w][idx] : 0u;
            ci[jj] = (idx < nc) ? candI[w][idx] : 0;
        }
        unsigned t = 0u;
        for (int bit = 31; bit >= 0; bit--) {
            unsigned tt = t | (1u << bit);
            int c = 0;
#pragma unroll
            for (int jj = 0; jj < CAP_/32; jj++) c += (cu[jj] >= tt);
            c = __reduce_add_sync(0xffffffffu, c);
            if (c >= TOPK_) {
                t = tt;
                if (c == TOPK_) break;
            }
        }
        X = t;

        int g1 = 0, g2 = 0;
#pragma unroll
        for (int jj = 0; jj < CAP_/32; jj++) {
            int idx = lane + jj * 32;
            bool valid = (idx < nc);
            unsigned x = cu[jj];
            bool gt = valid && (x > X), eq = valid && (x == X);
            unsigned mg = __ballot_sync(0xffffffffu, gt);
            unsigned me = __ballot_sync(0xffffffffu, eq);
            if (gt) {
                int p = g1 + __popc(mg & ltmask);
                sk[w][p] = ci[jj];
                sv[w][p] = funflip(x);
            }
            if (eq) {
                int p = g2 + __popc(me & ltmask);
                if (p < 64) ek[w][p] = ci[jj];
            }
            g1 += __popc(mg);
            g2 += __popc(me);
        }
        __syncwarp();
        if (lane == 0) {
            int need = TOPK_ - g1;
            int ec   = g2 > 64 ? 64 : g2;
            float xv = funflip(X);
            for (int s2 = 0; s2 < need; s2++) {
                int best = 0x7FFFFFFF, bi = 0;
                for (int e = 0; e < ec; e++) {
                    int v2 = ek[w][e];
                    if (v2 < best) { best = v2; bi = e; }
                }
                ek[w][bi] = 0x7FFFFFFF;
                sk[w][g1 + s2] = best;
                sv[w][g1 + s2] = xv;
            }
        }
    } else {
        unsigned t = 0u;
        for (int bit = 31; bit >= 0; bit--) {
            unsigned tt = t | (1u << bit);
            int c = 0;
#pragma unroll
            for (int i = 0; i < 64; i++) c += (u[i] >= tt);
            c = __reduce_add_sync(0xffffffffu, c);
            if (c >= TOPK_) {
                t = tt;
                if (c == TOPK_) break;
            }
        }
        X = t;
        int g1 = 0, g2 = 0;
        for (int i = 0; i < 64; i++) {
            unsigned x = u[i];
            int kix = (i >> 2) * 128 + lane * 4 + (i & 3);
            bool gt = (x > X), eq = (x == X);
            unsigned mg = __ballot_sync(0xffffffffu, gt);
            unsigned me = __ballot_sync(0xffffffffu, eq);
            if (gt) {
                int p = g1 + __popc(mg & ltmask);
                sk[w][p] = kix;
                sv[w][p] = funflip(x);
            }
            if (eq) {
                int p = g2 + __popc(me & ltmask);
                if (p < 64) ek[w][p] = kix;
            }
            g1 += __popc(mg);
            g2 += __popc(me);
        }
        __syncwarp();
        if (lane == 0) {
            int need = TOPK_ - g1;
            int ec   = g2 > 64 ? 64 : g2;
            float xv = funflip(X);
            for (int s2 = 0; s2 < need; s2++) {
                int best = 0x7FFFFFFF, bi = 0;
                for (int e = 0; e < ec; e++) {
                    int v2 = ek[w][e];
                    if (v2 < best) { best = v2; bi = e; }
                }
                ek[w][bi] = 0x7FFFFFFF;
                sk[w][g1 + s2] = best;
                sv[w][g1 + s2] = xv;
            }
        }
    }
    __syncwarp();

    float v0 = sv[w][lane];
    float v1 = sv[w][lane + 32];
    float mx = funflip(__reduce_max_sync(0xffffffffu,
                 (unsigned)max(fflip(v0), fflip(v1))));
    float p0 = expf(v0 - mx);
    float p1 = expf(v1 - mx);
    pw[w][lane]      = p0;
    pw[w][lane + 32] = p1;
    float z = p0 + p1;
#pragma unroll
    for (int offx = 16; offx > 0; offx >>= 1)
        z += __shfl_xor_sync(0xffffffffu, z, offx);
    float invZ = 1.0f / z;

    const float* Vb = g_Vh + (size_t)bh * N_ * D_;
    float acc0 = 0.f, acc1 = 0.f;
#pragma unroll 8
    for (int j = 0; j < 64; j++) {
        float p  = pw[w][j];
        int   kj = sk[w][j];
        acc0 += p * __ldg(Vb + (size_t)kj * D_ + lane);
        acc1 += p * __ldg(Vb + (size_t)kj * D_ + lane + 32);
    }

    int b = bh >> 4, h = bh & 15;
    size_t obase = ((size_t)(b * N_ + qr)) * HID_ + h * D_ + lane;
    g_ctx[obase]      = acc0 * invZ;
    g_ctx[obase + 32] = acc1 * invZ;
}

// ---------------------------------------------------------------------------
extern "C" void kernel_launch(void* const* d_in, const int* in_sizes, int n_in,
                              void* d_out, int out_size)
{
    const float* q    = (const float*)d_in[0];
    const float* k    = (const float*)d_in[1];
    const float* v    = (const float*)d_in[2];
    const float* wq_w = (const float*)d_in[5];
    const float* wq_b = (const float*)d_in[6];
    const float* wk_w = (const float*)d_in[7];
    const float* wk_b = (const float*)d_in[8];
    const float* wv_w = (const float*)d_in[9];
    const float* wv_b = (const float*)d_in[10];
    const float* wo_w = (const float*)d_in[11];
    const float* wo_b = (const float*)d_in[12];
    float* out = (float*)d_out;

    float *Vh, *ctx;
    cudaGetSymbolAddress((void**)&Vh,  g_Vh);
    cudaGetSymbolAddress((void**)&ctx, g_ctx);

    cudaFuncSetAttribute(scores_s3r,
                         cudaFuncAttributeMaxDynamicSharedMemorySize, 6 * TSB_);
    cudaFuncSetAttribute(fused_front,
                         cudaFuncAttributeMaxDynamicSharedMemorySize, 2 * STGB_);
    cudaFuncSetAttribute(hmma_o,
                         cudaFuncAttributeMaxDynamicSharedMemorySize, 2 * STGB_);

    // Q/K fp32 projections (split3 epilogue) + V HMMA proj (double-buffered)
    fused_front<<<768, 256, 2 * STGB_>>>(q, wq_w, wq_b,
                                         k, wk_w, wk_b,
                                         v, wv_w, wv_b, Vh);

    // scores: 6-pass split-3 bf16 HMMA, resident tiles, flipped-bit output
    dim3 gSc(N_ / 128, N_ / 128, BH_);    // 16 x 16 x 32
    scores_s3r<<<gSc, 256, 6 * TSB_>>>();

    // exact top-64 + softmax + PV (8 warps/block)
    topk_pv_kernel<<<(B_ * N_ * H_) / 8, 256>>>();

    // O projection (on-the-fly split HMMA, double-buffered)
    dim3 gO(HID_ / 128, M_ / 128);        // 8 x 32
    hmma_o<<<gO, 256, 2 * STGB_>>>(ctx, wo_w, wo_b, out);
}

// round 16
// speedup vs baseline: 1.0132x; 1.0132x over previous
#include <cuda_runtime.h>
#include <cuda_bf16.h>
#include <cstdint>
#include <cstddef>
#include <math.h>

#define B_   2
#define N_   2048
#define HID_ 1024
#define H_   16
#define D_   64
#define BH_  (B_*H_)     // 32
#define M_   (B_*N_)     // 4096
#define TOPK_ 64

// scratch
__device__ float g_Vh[BH_*N_*D_];
__device__ unsigned g_S[134217728];           // 537 MB [bh][q][k]  FLIPPED fp32 bits
__device__ float g_ctx[M_*HID_];

// 3-term splits of (projected, scaled) Q / K  (h/m/l each), written directly
// by the projection epilogue
__device__ __nv_bfloat16 g_Q3[3][BH_*N_*D_];
__device__ __nv_bfloat16 g_K3[3][BH_*N_*D_];

// ---------------------------------------------------------------------------
#define LDSM_X4(r0,r1,r2,r3,addr) \
    asm volatile("ldmatrix.sync.aligned.m8n8.x4.shared.b16 {%0,%1,%2,%3}, [%4];" \
        : "=r"(r0), "=r"(r1), "=r"(r2), "=r"(r3) : "r"(addr))
#define LDSM_X2(r0,r1,addr) \
    asm volatile("ldmatrix.sync.aligned.m8n8.x2.shared.b16 {%0,%1}, [%2];" \
        : "=r"(r0), "=r"(r1) : "r"(addr))
#define MMA16816(c0,c1,c2,c3,a0,a1,a2,a3,b0,b1) \
    asm volatile("mma.sync.aligned.m16n8k16.row.col.f32.bf16.bf16.f32 " \
        "{%0,%1,%2,%3}, {%4,%5,%6,%7}, {%8,%9}, {%0,%1,%2,%3};" \
        : "+f"(c0), "+f"(c1), "+f"(c2), "+f"(c3) \
        : "r"(a0), "r"(a1), "r"(a2), "r"(a3), "r"(b0), "r"(b1))

__device__ __forceinline__ uint32_t smem_u32(const void* p) {
    uint32_t a;
    asm("{ .reg .u64 t; cvta.to.shared.u64 t, %1; cvt.u32.u64 %0, t; }"
        : "=r"(a) : "l"(p));
    return a;
}
__device__ __forceinline__ uint32_t bf2pack(__nv_bfloat16 a, __nv_bfloat16 b) {
    __nv_bfloat162 t; t.x = a; t.y = b;
    return *(uint32_t*)&t;
}
__device__ __forceinline__ unsigned fflip(float f) {
    unsigned u = __float_as_uint(f);
    return (u & 0x80000000u) ? ~u : (u | 0x80000000u);
}
__device__ __forceinline__ float funflip(unsigned u) {
    unsigned v = (u & 0x80000000u) ? (u & 0x7FFFFFFFu) : ~u;
    return __uint_as_float(v);
}

// ---------------------------------------------------------------------------
// fp32 SGEMM body (mainloop bit-identical); epilogue emits split3 bf16 planes
// ---------------------------------------------------------------------------
#define ASF(cur,kk,c) Asp[((cur)*8+(kk))*128+(c)]
#define BSF(cur,kk,c) Bsp[((cur)*8+(kk))*128+(c)]

__device__ __forceinline__ void sgemm_split3_body(
    const float* __restrict__ X, const float* __restrict__ W,
    const float* __restrict__ bias,
    __nv_bfloat16* __restrict__ Oh, __nv_bfloat16* __restrict__ Om,
    __nv_bfloat16* __restrict__ Ol,
    float oscale, int n0, int o0, char* fbuf)
{
    const int K = HID_;
    float* Asp = (float*)fbuf;            // [2][8][128] = 8192 B
    float* Bsp = (float*)(fbuf + 8192);   // 8192 B
    int tid = threadIdx.x;

    int lrow = tid >> 1;
    int lkq  = (tid & 1) * 4;
    const float* Xp = X + (size_t)(n0 + lrow) * K + lkq;
    const float* Wp = W + (size_t)(o0 + lrow) * K + lkq;

    {
        float4 xa = *(const float4*)Xp;
        float4 wa = *(const float4*)Wp;
        ASF(0, lkq+0, lrow) = xa.x; ASF(0, lkq+1, lrow) = xa.y;
        ASF(0, lkq+2, lrow) = xa.z; ASF(0, lkq+3, lrow) = xa.w;
        BSF(0, lkq+0, lrow) = wa.x; BSF(0, lkq+1, lrow) = wa.y;
        BSF(0, lkq+2, lrow) = wa.z; BSF(0, lkq+3, lrow) = wa.w;
    }
    __syncthreads();

    int tx = tid & 15, ty = tid >> 4;
    float c[8][8];
#pragma unroll
    for (int i = 0; i < 8; i++)
#pragma unroll
        for (int j = 0; j < 8; j++) c[i][j] = 0.f;

    const int NSTEP = K / 8;
#pragma unroll 2
    for (int k0 = 0; k0 < NSTEP; k0++) {
        int cur = k0 & 1;
        float4 xn, wn;
        if (k0 < NSTEP - 1) {
            xn = *(const float4*)(Xp + (k0 + 1) * 8);
            wn = *(const float4*)(Wp + (k0 + 1) * 8);
        }
#pragma unroll
        for (int kk = 0; kk < 8; kk++) {
            float a[8], b[8];
            *(float4*)&a[0] = *(const float4*)&ASF(cur, kk, ty*8);
            *(float4*)&a[4] = *(const float4*)&ASF(cur, kk, ty*8+4);
            *(float4*)&b[0] = *(const float4*)&BSF(cur, kk, tx*8);
            *(float4*)&b[4] = *(const float4*)&BSF(cur, kk, tx*8+4);
#pragma unroll
            for (int i = 0; i < 8; i++)
#pragma unroll
                for (int j = 0; j < 8; j++)
                    c[i][j] += a[i] * b[j];
        }
        if (k0 < NSTEP - 1) {
            int nxt = cur ^ 1;
            ASF(nxt, lkq+0, lrow) = xn.x; ASF(nxt, lkq+1, lrow) = xn.y;
            ASF(nxt, lkq+2, lrow) = xn.z; ASF(nxt, lkq+3, lrow) = xn.w;
            BSF(nxt, lkq+0, lrow) = wn.x; BSF(nxt, lkq+1, lrow) = wn.y;
            BSF(nxt, lkq+2, lrow) = wn.z; BSF(nxt, lkq+3, lrow) = wn.w;
            __syncthreads();
        }
    }

    float bfr[8];
#pragma unroll
    for (int j = 0; j < 8; j++) bfr[j] = __ldg(bias + o0 + tx*8 + j);

#pragma unroll
    for (int i = 0; i < 8; i++) {
        int n = n0 + ty * 8 + i;
        int o = o0 + tx * 8;
        int b = n >> 11, nn = n & 2047;
        int h = o >> 6,  d  = o & 63;
        size_t idx = (((size_t)(b * H_ + h) * N_) + nn) * D_ + d;

        float val[8];
#pragma unroll
        for (int j = 0; j < 8; j++) val[j] = (c[i][j] + bfr[j]) * oscale;

        __nv_bfloat16 hh[8], mm[8], ll[8];
#pragma unroll
        for (int j = 0; j < 8; j++) {
            hh[j] = __float2bfloat16_rn(val[j]);
            float r1 = val[j] - __bfloat162float(hh[j]);
            mm[j] = __float2bfloat16_rn(r1);
            float r2 = r1 - __bfloat162float(mm[j]);
            ll[j] = __float2bfloat16_rn(r2);
        }
        uint4 hv, mv, lv;
        hv.x = bf2pack(hh[0], hh[1]); hv.y = bf2pack(hh[2], hh[3]);
        hv.z = bf2pack(hh[4], hh[5]); hv.w = bf2pack(hh[6], hh[7]);
        mv.x = bf2pack(mm[0], mm[1]); mv.y = bf2pack(mm[2], mm[3]);
        mv.z = bf2pack(mm[4], mm[5]); mv.w = bf2pack(mm[6], mm[7]);
        lv.x = bf2pack(ll[0], ll[1]); lv.y = bf2pack(ll[2], ll[3]);
        lv.z = bf2pack(ll[4], ll[5]); lv.w = bf2pack(ll[6], ll[7]);
        *(uint4*)(Oh + idx) = hv;
        *(uint4*)(Om + idx) = mv;
        *(uint4*)(Ol + idx) = lv;
    }
}

// ---------------------------------------------------------------------------
// HMMA split-bf16 GEMM body with ON-THE-FLY fp32 -> hi/lo split
// (single 40KB stage, register prefetch, 2 syncs/kc — R12 proven variant)
// ---------------------------------------------------------------------------
#define TS_   5120          // tile size in bf16 entries (128 rows * 40)

__device__ __forceinline__ void hmma_f32_body(
    const float* __restrict__ Af, const float* __restrict__ Bf,
    const float* __restrict__ bias, float* __restrict__ Out,
    int mode, int n0, int o0, char* fbuf)
{
    __nv_bfloat16* smbuf = (__nv_bfloat16*)fbuf;   // 4 tiles, 40960 B
    int tid  = threadIdx.x;
    int wid  = tid >> 5, lane = tid & 31;
    int wm   = wid >> 2;
    int wn   = wid & 3;

    uint32_t smb = smem_u32(smbuf);

    float c[4][4][4];
#pragma unroll
    for (int mt = 0; mt < 4; mt++)
#pragma unroll
        for (int nt = 0; nt < 4; nt++)
#pragma unroll
            for (int r = 0; r < 4; r++) c[mt][nt][r] = 0.f;

    int rowm[4], segm[4];
    const float* gbase[4];
#pragma unroll
    for (int j = 0; j < 4; j++) {
        int isB  = j >> 1;
        int sub  = ((j & 1) << 8) + tid;       // 0..511
        rowm[j] = sub >> 2; segm[j] = sub & 3;
        const float* base = isB ? Bf : Af;
        int grow = (isB ? o0 : n0) + rowm[j];
        gbase[j] = base + (size_t)grow * HID_ + segm[j] * 8;
    }
    uint32_t soffh[4], soffl[4];
#pragma unroll
    for (int j = 0; j < 4; j++) {
        int isB = j >> 1;
        uint32_t e = (uint32_t)(rowm[j] * 40 + segm[j] * 8);
        soffh[j] = (uint32_t)(((isB ? 2 : 0) * TS_ + e) * 2);
        soffl[j] = (uint32_t)(((isB ? 3 : 1) * TS_ + e) * 2);
    }

    uint32_t laneA = (uint32_t)((lane & 15) * 80 + (lane >> 4) * 16);
    uint32_t laneB = (uint32_t)((lane & 7) * 80 + ((lane >> 3) & 1) * 16);
    uint32_t aBase0 = smb + (uint32_t)(wm * 64 * 80) + laneA;
    uint32_t bBase0 = smb + (uint32_t)(wn * 32 * 80) + laneB;

    float4 pf0[4], pf1[4];
#pragma unroll
    for (int j = 0; j < 4; j++) {
        pf0[j] = *(const float4*)gbase[j];
        pf1[j] = *(const float4*)(gbase[j] + 4);
    }
#pragma unroll
    for (int j = 0; j < 4; j++) {
        float fv[8] = {pf0[j].x, pf0[j].y, pf0[j].z, pf0[j].w,
                       pf1[j].x, pf1[j].y, pf1[j].z, pf1[j].w};
        __nv_bfloat16 hh[8], ll[8];
#pragma unroll
        for (int e = 0; e < 8; e++) {
            hh[e] = __float2bfloat16_rn(fv[e]);
            ll[e] = __float2bfloat16_rn(fv[e] - __bfloat162float(hh[e]));
        }
        uint4 hv, lv;
        hv.x = bf2pack(hh[0], hh[1]); hv.y = bf2pack(hh[2], hh[3]);
        hv.z = bf2pack(hh[4], hh[5]); hv.w = bf2pack(hh[6], hh[7]);
        lv.x = bf2pack(ll[0], ll[1]); lv.y = bf2pack(ll[2], ll[3]);
        lv.z = bf2pack(ll[4], ll[5]); lv.w = bf2pack(ll[6], ll[7]);
        *(uint4*)((char*)smbuf + soffh[j]) = hv;
        *(uint4*)((char*)smbuf + soffl[j]) = lv;
    }
    __syncthreads();

    for (int kc = 0; kc < 32; kc++) {
        if (kc < 31) {
#pragma unroll
            for (int j = 0; j < 4; j++) {
                pf0[j] = *(const float4*)(gbase[j] + (kc + 1) * 32);
                pf1[j] = *(const float4*)(gbase[j] + (kc + 1) * 32 + 4);
            }
        }

#pragma unroll
        for (int pass = 0; pass < 3; pass++) {
            uint32_t aT = aBase0 + (uint32_t)(((pass == 2) ? TS_ : 0) * 2);
            uint32_t bT = bBase0 + (uint32_t)((((pass == 1) ? 3 : 2) * TS_) * 2);
#pragma unroll
            for (int k16 = 0; k16 < 2; k16++) {
                uint32_t a[4][4];
#pragma unroll
                for (int mt = 0; mt < 4; mt++)
                    LDSM_X4(a[mt][0], a[mt][1], a[mt][2], a[mt][3],
                            aT + (uint32_t)(mt * 1280 + k16 * 32));
                uint32_t bf[4][2];
#pragma unroll
                for (int nt = 0; nt < 4; nt++)
                    LDSM_X2(bf[nt][0], bf[nt][1],
                            bT + (uint32_t)(nt * 640 + k16 * 32));
#pragma unroll
                for (int mt = 0; mt < 4; mt++)
#pragma unroll
                    for (int nt = 0; nt < 4; nt++)
                        MMA16816(c[mt][nt][0], c[mt][nt][1], c[mt][nt][2], c[mt][nt][3],
                                 a[mt][0], a[mt][1], a[mt][2], a[mt][3],
                                 bf[nt][0], bf[nt][1]);
            }
        }

        if (kc < 31) {
            __syncthreads();
#pragma unroll
            for (int j = 0; j < 4; j++) {
                float fv[8] = {pf0[j].x, pf0[j].y, pf0[j].z, pf0[j].w,
                               pf1[j].x, pf1[j].y, pf1[j].z, pf1[j].w};
                __nv_bfloat16 hh[8], ll[8];
#pragma unroll
                for (int e = 0; e < 8; e++) {
                    hh[e] = __float2bfloat16_rn(fv[e]);
                    ll[e] = __float2bfloat16_rn(fv[e] - __bfloat162float(hh[e]));
                }
                uint4 hv, lv;
                hv.x = bf2pack(hh[0], hh[1]); hv.y = bf2pack(hh[2], hh[3]);
                hv.z = bf2pack(hh[4], hh[5]); hv.w = bf2pack(hh[6], hh[7]);
                lv.x = bf2pack(ll[0], ll[1]); lv.y = bf2pack(ll[2], ll[3]);
                lv.z = bf2pack(ll[4], ll[5]); lv.w = bf2pack(ll[6], ll[7]);
                *(uint4*)((char*)smbuf + soffh[j]) = hv;
                *(uint4*)((char*)smbuf + soffl[j]) = lv;
            }
            __syncthreads();
        }
    }

    int row_l = lane >> 2;
    int col_l = (lane & 3) * 2;
#pragma unroll
    for (int nt = 0; nt < 4; nt++) {
        int o = o0 + wn * 32 + nt * 8 + col_l;
        float bv0 = __ldg(bias + o);
        float bv1 = __ldg(bias + o + 1);
#pragma unroll
        for (int mt = 0; mt < 4; mt++) {
            int n = n0 + wm * 64 + mt * 16 + row_l;
#pragma unroll
            for (int half = 0; half < 2; half++) {
                int nn2 = n + half * 8;
                size_t idx;
                if (mode == 0) {
                    int b = nn2 >> 11, nr = nn2 & 2047;
                    int h = o >> 6,  d0 = o & 63;
                    idx = (((size_t)(b * H_ + h) * N_) + nr) * D_ + d0;
                } else {
                    idx = (size_t)nn2 * HID_ + o;
                }
                float2 vv;
                vv.x = c[mt][nt][half * 2 + 0] + bv0;
                vv.y = c[mt][nt][half * 2 + 1] + bv1;
                *(float2*)(Out + idx) = vv;
            }
        }
    }
}

// ---------------------------------------------------------------------------
// fused_front: Q/K fp32 proj (split3 epilogue) + V HMMA proj
// ---------------------------------------------------------------------------
__global__ __launch_bounds__(256, 2) void fused_front(
    const float* __restrict__ q,  const float* __restrict__ wq_w,
    const float* __restrict__ wq_b,
    const float* __restrict__ k,  const float* __restrict__ wk_w,
    const float* __restrict__ wk_b,
    const float* __restrict__ v,  const float* __restrict__ wv_w,
    const float* __restrict__ wv_b, float* __restrict__ Vh)
{
    __shared__ __align__(16) char fbuf[40960];
    int id = blockIdx.x;
    int r  = id % 3;
    int g  = id / 3;

    if (r < 2) {
        int t   = g * 2 + r;          // 0..511
        int z   = t >> 8;             // 0 = Q, 1 = K
        int rem = t & 255;
        int o0  = (rem & 7) * 128;
        int n0  = (rem >> 3) * 128;
        if (z == 0)
            sgemm_split3_body(q, wq_w, wq_b,
                              g_Q3[0], g_Q3[1], g_Q3[2],
                              0.125f, n0, o0, fbuf);
        else
            sgemm_split3_body(k, wk_w, wk_b,
                              g_K3[0], g_K3[1], g_K3[2],
                              1.0f, n0, o0, fbuf);
    } else {
        int t  = g;                   // 0..255
        int o0 = (t & 7) * 128;
        int n0 = (t >> 3) * 128;
        hmma_f32_body(v, wv_w, wv_b, Vh, 0, n0, o0, fbuf);
    }
}

// O projection standalone (after topk)
__global__ __launch_bounds__(256, 2) void hmma_o(
    const float* __restrict__ ctx, const float* __restrict__ wo_w,
    const float* __restrict__ wo_b, float* __restrict__ Out)
{
    __shared__ __align__(16) char fbuf[40960];
    hmma_f32_body(ctx, wo_w, wo_b, Out, 1,
                  blockIdx.y * 128, blockIdx.x * 128, fbuf);
}

// ---------------------------------------------------------------------------
// Scores (resident tiles) -- epilogue stores FLIPPED bits.
// ---------------------------------------------------------------------------
#define STRB_ 144                 // row stride bytes
#define TSB_  (128 * STRB_)       // tile bytes = 18432

__global__ __launch_bounds__(256, 2) void scores_s3r(void)
{
    extern __shared__ __align__(16) char dsm[];
    int tid  = threadIdx.x;
    int wid  = tid >> 5, lane = tid & 31;
    int wm   = wid >> 2;
    int wn   = wid & 3;
    int bh   = blockIdx.z;
    int k0   = blockIdx.x * 128;
    int q0   = blockIdx.y * 128;

    uint32_t smb = smem_u32(dsm);

    const __nv_bfloat16* tsrc[6] = {
        g_Q3[0] + (size_t)bh * N_ * D_, g_Q3[1] + (size_t)bh * N_ * D_,
        g_Q3[2] + (size_t)bh * N_ * D_, g_K3[0] + (size_t)bh * N_ * D_,
        g_K3[1] + (size_t)bh * N_ * D_, g_K3[2] + (size_t)bh * N_ * D_ };

#pragma unroll
    for (int t = 0; t < 6; t++) {
        int r0 = (t < 3) ? q0 : k0;
#pragma unroll
        for (int it = 0; it < 4; it++) {
            int sub = it * 256 + tid;
            int row = sub >> 3, seg = sub & 7;
            *(uint4*)(dsm + t * TSB_ + row * STRB_ + seg * 16) =
                *(const uint4*)(tsrc[t] + (size_t)(r0 + row) * D_ + seg * 8);
        }
    }
    __syncthreads();

    float c[4][4][4];
#pragma unroll
    for (int mt = 0; mt < 4; mt++)
#pragma unroll
        for (int nt = 0; nt < 4; nt++)
#pragma unroll
            for (int r = 0; r < 4; r++) c[mt][nt][r] = 0.f;

    uint32_t laneA = (uint32_t)((lane & 15) * STRB_ + (lane >> 4) * 16);
    uint32_t laneB = (uint32_t)((lane & 7) * STRB_ + ((lane >> 3) & 1) * 16);
    uint32_t aBase0 = smb + (uint32_t)(wm * 64 * STRB_) + laneA;
    uint32_t bBase0 = smb + (uint32_t)(wn * 32 * STRB_) + laneB;

#pragma unroll
    for (int rnd = 0; rnd < 2; rnd++) {
#pragma unroll
        for (int kc = 0; kc < 2; kc++) {
            int npass = rnd ? 2 : 4;
            for (int p = 0; p < npass; p++) {
                int at, bt;
                if (rnd == 0) { at = p >> 1;           bt = 3 + (p & 1); }
                else          { at = (p == 0) ? 0 : 2; bt = (p == 0) ? 5 : 3; }
                uint32_t aT = aBase0 + (uint32_t)(at * TSB_);
                uint32_t bT = bBase0 + (uint32_t)(bt * TSB_);
#pragma unroll
                for (int k16 = 0; k16 < 2; k16++) {
                    uint32_t coloff = (uint32_t)(kc * 64 + k16 * 32);
                    uint32_t a[4][4];
#pragma unroll
                    for (int mt = 0; mt < 4; mt++)
                        LDSM_X4(a[mt][0], a[mt][1], a[mt][2], a[mt][3],
                                aT + (uint32_t)(mt * 16 * STRB_) + coloff);
                    uint32_t bf[4][2];
#pragma unroll
                    for (int nt = 0; nt < 4; nt++)
                        LDSM_X2(bf[nt][0], bf[nt][1],
                                bT + (uint32_t)(nt * 8 * STRB_) + coloff);
#pragma unroll
                    for (int mt = 0; mt < 4; mt++)
#pragma unroll
                        for (int nt = 0; nt < 4; nt++)
                            MMA16816(c[mt][nt][0], c[mt][nt][1], c[mt][nt][2], c[mt][nt][3],
                                     a[mt][0], a[mt][1], a[mt][2], a[mt][3],
                                     bf[nt][0], bf[nt][1]);
                }
            }
        }
    }

    int row_l = lane >> 2;
    int col_l = (lane & 3) * 2;
    unsigned* Sb = g_S + (size_t)bh * N_ * N_;
#pragma unroll
    for (int nt = 0; nt < 4; nt++) {
        int o = k0 + wn * 32 + nt * 8 + col_l;
#pragma unroll
        for (int mt = 0; mt < 4; mt++) {
            int n = q0 + wm * 64 + mt * 16 + row_l;
#pragma unroll
            for (int half = 0; half < 2; half++) {
                int qq = n + half * 8;
                uint2 vv;
                vv.x = fflip(c[mt][nt][half * 2 + 0]);
                vv.y = fflip(c[mt][nt][half * 2 + 1]);
                *(uint2*)(Sb + (size_t)qq * N_ + o) = vv;
            }
        }
    }
}

// ---------------------------------------------------------------------------
// topk_v4 (selection verbatim R12), 8 warps/block; PV float2-vectorized
// (lane handles dims 2*lane, 2*lane+1; per-dim FFMA chain bit-identical).
// ---------------------------------------------------------------------------
#define CAP_ 320

__global__ __launch_bounds__(256) void topk_pv_kernel(void)
{
    __shared__ unsigned       candV[8][CAP_];
    __shared__ unsigned short candI[8][CAP_];
    __shared__ int   sk[8][64];
    __shared__ float sv[8][64];
    __shared__ float pw[8][64];
    __shared__ int   ek[8][64];

    int w    = threadIdx.x >> 5;
    int lane = threadIdx.x & 31;
    int gq   = blockIdx.x * 8 + w;
    int bh   = gq >> 11;
    int qr   = gq & 2047;
    unsigned ltmask = (1u << lane) - 1u;

    const unsigned* Sb = g_S + ((size_t)bh * N_ + qr) * N_;

    unsigned u[64];
    unsigned m1 = 0u, m2 = 0u;
#pragma unroll
    for (int it = 0; it < 16; it++) {
        uint4 f = ((const uint4*)Sb)[it * 32 + lane];
        u[it*4+0] = f.x; u[it*4+1] = f.y; u[it*4+2] = f.z; u[it*4+3] = f.w;
#pragma unroll
        for (int r = 0; r < 4; r++) {
            unsigned x = u[it*4+r];
            if (x > m1) { m2 = m1; m1 = x; }
            else if (x > m2) { m2 = x; }
        }
    }
    unsigned T0 = __reduce_min_sync(0xffffffffu, m2);

    int cnt = 0;
#pragma unroll
    for (int i = 0; i < 64; i++) cnt += (u[i] >= T0);
    int off = cnt;
#pragma unroll
    for (int d = 1; d < 32; d <<= 1) {
        int t = __shfl_up_sync(0xffffffffu, off, d);
        if (lane >= d) off += t;
    }
    int nc = __shfl_sync(0xffffffffu, off, 31);
    off -= cnt;

    if (nc <= CAP_) {
        int o2 = off;
#pragma unroll
        for (int i = 0; i < 64; i++) {
            if (u[i] >= T0) {
                candV[w][o2] = u[i];
                candI[w][o2] = (unsigned short)((i >> 2) * 128 + lane * 4 + (i & 3));
                o2++;
            }
        }
    }
    __syncwarp();

    unsigned X = 0u;
    if (nc <= CAP_) {
        unsigned cu[CAP_/32];
        unsigned short ci[CAP_/32];
#pragma unroll
        for (int jj = 0; jj < CAP_/32; jj++) {
            int idx = lane + jj * 32;
            cu[jj] = (idx < nc) ? candV[w][idx] : 0u;
            ci[jj] = (idx < nc) ? candI[w][idx] : 0;
        }
        unsigned t = 0u;
        for (int bit = 31; bit >= 0; bit--) {
            unsigned tt = t | (1u << bit);
            int c = 0;
#pragma unroll
            for (int jj = 0; jj < CAP_/32; jj++) c += (cu[jj] >= tt);
            c = __reduce_add_sync(0xffffffffu, c);
            if (c >= TOPK_) {
                t = tt;
                if (c == TOPK_) break;
            }
        }
        X = t;

        int g1 = 0, g2 = 0;
#pragma unroll
        for (int jj = 0; jj < CAP_/32; jj++) {
            int idx = lane + jj * 32;
            bool valid = (idx < nc);
            unsigned x = cu[jj];
            bool gt = valid && (x > X), eq = valid && (x == X);
            unsigned mg = __ballot_sync(0xffffffffu, gt);
            unsigned me = __ballot_sync(0xffffffffu, eq);
            if (gt) {
                int p = g1 + __popc(mg & ltmask);
                sk[w][p] = ci[jj];
                sv[w][p] = funflip(x);
            }
            if (eq) {
                int p = g2 + __popc(me & ltmask);
                if (p < 64) ek[w][p] = ci[jj];
            }
            g1 += __popc(mg);
            g2 += __popc(me);
        }
        __syncwarp();
        if (lane == 0) {
            int need = TOPK_ - g1;
            int ec   = g2 > 64 ? 64 : g2;
            float xv = funflip(X);
            for (int s2 = 0; s2 < need; s2++) {
                int best = 0x7FFFFFFF, bi = 0;
                for (int e = 0; e < ec; e++) {
                    int v2 = ek[w][e];
                    if (v2 < best) { best = v2; bi = e; }
                }
                ek[w][bi] = 0x7FFFFFFF;
                sk[w][g1 + s2] = best;
                sv[w][g1 + s2] = xv;
            }
        }
    } else {
        unsigned t = 0u;
        for (int bit = 31; bit >= 0; bit--) {
            unsigned tt = t | (1u << bit);
            int c = 0;
#pragma unroll
            for (int i = 0; i < 64; i++) c += (u[i] >= tt);
            c = __reduce_add_sync(0xffffffffu, c);
            if (c >= TOPK_) {
                t = tt;
                if (c == TOPK_) break;
            }
        }
        X = t;
        int g1 = 0, g2 = 0;
        for (int i = 0; i < 64; i++) {
            unsigned x = u[i];
            int kix = (i >> 2) * 128 + lane * 4 + (i & 3);
            bool gt = (x > X), eq = (x == X);
            unsigned mg = __ballot_sync(0xffffffffu, gt);
            unsigned me = __ballot_sync(0xffffffffu, eq);
            if (gt) {
                int p = g1 + __popc(mg & ltmask);
                sk[w][p] = kix;
                sv[w][p] = funflip(x);
            }
            if (eq) {
                int p = g2 + __popc(me & ltmask);
                if (p < 64) ek[w][p] = kix;
            }
            g1 += __popc(mg);
            g2 += __popc(me);
        }
        __syncwarp();
        if (lane == 0) {
            int need = TOPK_ - g1;
            int ec   = g2 > 64 ? 64 : g2;
            float xv = funflip(X);
            for (int s2 = 0; s2 < need; s2++) {
                int best = 0x7FFFFFFF, bi = 0;
                for (int e = 0; e < ec; e++) {
                    int v2 = ek[w][e];
                    if (v2 < best) { best = v2; bi = e; }
                }
                ek[w][bi] = 0x7FFFFFFF;
                sk[w][g1 + s2] = best;
                sv[w][g1 + s2] = xv;
            }
        }
    }
    __syncwarp();

    // softmax over selected 64
    float v0 = sv[w][lane];
    float v1 = sv[w][lane + 32];
    float mx = funflip(__reduce_max_sync(0xffffffffu,
                 (unsigned)max(fflip(v0), fflip(v1))));
    float p0 = expf(v0 - mx);
    float p1 = expf(v1 - mx);
    pw[w][lane]      = p0;
    pw[w][lane + 32] = p1;
    float z = p0 + p1;
#pragma unroll
    for (int offx = 16; offx > 0; offx >>= 1)
        z += __shfl_xor_sync(0xffffffffu, z, offx);
    float invZ = 1.0f / z;

    // PV: lane covers dims (2*lane, 2*lane+1); float2 loads, same j-order
    const float* Vb = g_Vh + (size_t)bh * N_ * D_;
    float acc0 = 0.f, acc1 = 0.f;
#pragma unroll 8
    for (int j = 0; j < 64; j++) {
        float p  = pw[w][j];
        int   kj = sk[w][j];
        float2 vv = __ldg((const float2*)(Vb + (size_t)kj * D_ + lane * 2));
        acc0 += p * vv.x;
        acc1 += p * vv.y;
    }

    int b = bh >> 4, h = bh & 15;
    size_t obase = ((size_t)(b * N_ + qr)) * HID_ + h * D_ + lane * 2;
    float2 outv;
    outv.x = acc0 * invZ;
    outv.y = acc1 * invZ;
    *(float2*)(g_ctx + obase) = outv;
}

// ---------------------------------------------------------------------------
extern "C" void kernel_launch(void* const* d_in, const int* in_sizes, int n_in,
                              void* d_out, int out_size)
{
    const float* q    = (const float*)d_in[0];
    const float* k    = (const float*)d_in[1];
    const float* v    = (const float*)d_in[2];
    const float* wq_w = (const float*)d_in[5];
    const float* wq_b = (const float*)d_in[6];
    const float* wk_w = (const float*)d_in[7];
    const float* wk_b = (const float*)d_in[8];
    const float* wv_w = (const float*)d_in[9];
    const float* wv_b = (const float*)d_in[10];
    const float* wo_w = (const float*)d_in[11];
    const float* wo_b = (const float*)d_in[12];
    float* out = (float*)d_out;

    float *Vh, *ctx;
    cudaGetSymbolAddress((void**)&Vh,  g_Vh);
    cudaGetSymbolAddress((void**)&ctx, g_ctx);

    cudaFuncSetAttribute(scores_s3r,
                         cudaFuncAttributeMaxDynamicSharedMemorySize, 6 * TSB_);

    // Q/K fp32 projections (split3 epilogue) + V HMMA proj
    fused_front<<<768, 256>>>(q, wq_w, wq_b,
                              k, wk_w, wk_b,
                              v, wv_w, wv_b, Vh);

    // scores: 6-pass split-3 bf16 HMMA, resident tiles, flipped-bit output
    dim3 gSc(N_ / 128, N_ / 128, BH_);    // 16 x 16 x 32
    scores_s3r<<<gSc, 256, 6 * TSB_>>>();

    // exact top-64 + softmax + PV (8 warps/block)
    topk_pv_kernel<<<(B_ * N_ * H_) / 8, 256>>>();

    // O projection (on-the-fly split HMMA)
    dim3 gO(HID_ / 128, M_ / 128);        // 8 x 32
    hmma_o<<<gO, 256>>>(ctx, wo_w, wo_b, out);
}